// round 15
// baseline (speedup 1.0000x reference)
#include <cuda_runtime.h>
#include <cstdint>

// Shapes (fixed by the problem)
#define BB   2048
#define TT   512
#define FF   64
#define HH   16
#define G4   64          // 4*H
#define BT   (BB*TT)     // 1,048,576 rows in the xz GEMM

// Scratch for xz = x@Wx + b : [B*T, 64] fp32 = 256 MiB (module global, allowed)
__device__ float g_xz[(size_t)BT * G4];

// ---------------- packed f32x2 helpers (family-wide PTX, sm_100+) ----------------
__device__ __forceinline__ unsigned long long pack2(float a, float b) {
    unsigned long long r;
    asm("mov.b64 %0, {%1, %2};" : "=l"(r) : "f"(a), "f"(b));
    return r;
}
__device__ __forceinline__ float2 unpack2(unsigned long long v) {
    float2 r;
    asm("mov.b64 {%0, %1}, %2;" : "=f"(r.x), "=f"(r.y) : "l"(v));
    return r;
}
__device__ __forceinline__ unsigned long long fma2(unsigned long long a,
                                                   unsigned long long b,
                                                   unsigned long long c) {
    unsigned long long d;
    asm("fma.rn.f32x2 %0, %1, %2, %3;" : "=l"(d) : "l"(a), "l"(b), "l"(c));
    return d;
}

// =====================================================================
// Kernel 1: xz = x @ Wx + b        [BT,64] = [BT,64]x[64,64] + [64]
//   CTA: 256 threads (8 warps), 128 rows per CTA (16 rows per warp).
//   SMEM: x staged as duplicated pairs {v,v} (64 KB) so the inner loop
//   feeds fma.rn.f32x2 with zero pack instructions; Wx verbatim (16 KB).
//   lane l owns output columns (2l, 2l+1).
// =====================================================================
__global__ void __launch_bounds__(256, 2)
gemm_xz_kernel(const float* __restrict__ x,
               const float* __restrict__ Wx,
               const float* __restrict__ b) {
    extern __shared__ unsigned char smem[];
    float4* sX4 = (float4*)smem;                        // [128 rows][32 f4]  64 KB
    float4* sW4 = (float4*)(smem + 65536);              // 1024 f4            16 KB

    const int tid = threadIdx.x;

    // ---- stage x block (128 rows x 64 f), duplicated per element ----
    {
        const float4* x4 = (const float4*)x;
        size_t base4 = (size_t)blockIdx.x * 2048;       // 128 rows * 16 float4
        #pragma unroll
        for (int i = 0; i < 8; i++) {
            int idx = tid + i * 256;
            float4 v = __ldcs(&x4[base4 + idx]);
            int row = idx >> 4;
            int f4  = idx & 15;
            sX4[row * 32 + f4 * 2]     = make_float4(v.x, v.x, v.y, v.y);
            sX4[row * 32 + f4 * 2 + 1] = make_float4(v.z, v.z, v.w, v.w);
        }
    }
    // ---- stage Wx verbatim: sW[f][j] row-major ----
    {
        const float4* w4 = (const float4*)Wx;
        #pragma unroll
        for (int i = 0; i < 4; i++) sW4[tid + i * 256] = w4[tid + i * 256];
    }
    __syncthreads();

    const int warp = tid >> 5;
    const int lane = tid & 31;
    const int rowbase = warp * 16;

    const ulonglong2*         sXv = (const ulonglong2*)smem;           // [row][32]
    const unsigned long long* sWu = (const unsigned long long*)(smem + 65536); // [f][32]

    unsigned long long acc[16];
    float2 bp = *(const float2*)(b + 2 * lane);
    unsigned long long binit = pack2(bp.x, bp.y);
    #pragma unroll
    for (int r = 0; r < 16; r++) acc[r] = binit;

    #pragma unroll 2
    for (int fp = 0; fp < 32; fp++) {
        // Wx pairs for f=2fp and f=2fp+1, columns (2l,2l+1): conflict-free LDS.64
        unsigned long long w0 = sWu[(2 * fp)     * 32 + lane];
        unsigned long long w1 = sWu[(2 * fp + 1) * 32 + lane];
        #pragma unroll
        for (int r = 0; r < 16; r++) {
            ulonglong2 xv = sXv[(rowbase + r) * 32 + fp];  // broadcast LDS.128
            acc[r] = fma2(xv.x, w0, acc[r]);               // {x[2fp],x[2fp]}     * {w,w'}
            acc[r] = fma2(xv.y, w1, acc[r]);               // {x[2fp+1],x[2fp+1]} * {w,w'}
        }
    }

    float2* out2 = (float2*)g_xz;
    size_t growbase = (size_t)blockIdx.x * 128 + rowbase;
    #pragma unroll
    for (int r = 0; r < 16; r++) {
        float2 res = unpack2(acc[r]);
        out2[(growbase + r) * 32 + lane] = res;            // coalesced 256B/warp
    }
}

// =====================================================================
// Kernel 2: LSTM recurrence + head. One warp per batch row.
//   z row [64] = gates [i(0:16) | f(16:32) | g(32:48) | o(48:64)]
//   lane l owns z pair (2l, 2l+1):
//     lanes 0-7: i | 8-15: f | 16-23: g | 24-31: o
//   h/c pairs live on lanes 0-7 (lane p holds h[2p], h[2p+1]).
// =====================================================================
__device__ __forceinline__ float sigm(float x) {
    return __fdividef(1.0f, 1.0f + __expf(-x));
}

__device__ __forceinline__ void lstm_step(float2 z, const float2* whp,
                                          float& h_lo, float& h_hi,
                                          float& c_lo, float& c_hi,
                                          bool isG, int bse) {
    const unsigned M = 0xffffffffu;
    float alo = z.x, ahi = z.y;       // xz already includes bias
    float blo = 0.f, bhi = 0.f;       // second chain for ILP
    #pragma unroll
    for (int k = 0; k < 16; k++) {
        float hk = __shfl_sync(M, (k & 1) ? h_hi : h_lo, k >> 1);
        if (k & 2) { blo = fmaf(hk, whp[k].x, blo); bhi = fmaf(hk, whp[k].y, bhi); }
        else       { alo = fmaf(hk, whp[k].x, alo); ahi = fmaf(hk, whp[k].y, ahi); }
    }
    alo += blo; ahi += bhi;

    float act_lo = isG ? fmaxf(alo, 0.f) : sigm(alo);
    float act_hi = isG ? fmaxf(ahi, 0.f) : sigm(ahi);

    // gather f,g,o pairs onto c-owner lanes 0-7; other lanes get benign garbage
    float f_lo = __shfl_sync(M, act_lo, bse + 8);
    float f_hi = __shfl_sync(M, act_hi, bse + 8);
    float g_lo = __shfl_sync(M, act_lo, bse + 16);
    float g_hi = __shfl_sync(M, act_hi, bse + 16);
    float o_lo = __shfl_sync(M, act_lo, bse + 24);
    float o_hi = __shfl_sync(M, act_hi, bse + 24);

    c_lo = fmaf(f_lo, c_lo, act_lo * g_lo);   // act_lo == i on lanes 0-7
    c_hi = fmaf(f_hi, c_hi, act_hi * g_hi);
    h_lo = o_lo * fmaxf(c_lo, 0.f);
    h_hi = o_hi * fmaxf(c_hi, 0.f);
}

__global__ void __launch_bounds__(128)
rnn_kernel(const float* __restrict__ Wh,
           const float* __restrict__ W2, const float* __restrict__ b2,
           const float* __restrict__ W3, const float* __restrict__ b3,
           const float* __restrict__ Wo, const float* __restrict__ bo,
           float* __restrict__ out) {
    const unsigned M = 0xffffffffu;
    const int warp = threadIdx.x >> 5;
    const int lane = threadIdx.x & 31;
    const int row  = blockIdx.x * 4 + warp;           // batch index

    // Wh column pairs for this lane's gates: {Wh[k][2l], Wh[k][2l+1]}
    float2 whp[16];
    #pragma unroll
    for (int k = 0; k < 16; k++)
        whp[k] = *(const float2*)(Wh + k * G4 + 2 * lane);

    const float2* zp = (const float2*)g_xz + (size_t)row * (TT * 32) + lane;

    // 4-deep prefetch ring (MLP for DRAM streaming of xz)
    float2 z0 = __ldcs(zp +  0);
    float2 z1 = __ldcs(zp + 32);
    float2 z2 = __ldcs(zp + 64);
    float2 z3 = __ldcs(zp + 96);

    float h_lo = 0.f, h_hi = 0.f, c_lo = 0.f, c_hi = 0.f;
    const bool isG = (lane >= 16 && lane < 24);
    const int  bse = lane & 7;

    #pragma unroll 1
    for (int t = 0; t < TT; t += 4) {
        lstm_step(z0, whp, h_lo, h_hi, c_lo, c_hi, isG, bse);
        { int tn = t + 4; if (tn >= TT) tn = 0; z0 = __ldcs(zp + tn * 32); }
        lstm_step(z1, whp, h_lo, h_hi, c_lo, c_hi, isG, bse);
        { int tn = t + 5; if (tn >= TT) tn = 1; z1 = __ldcs(zp + tn * 32); }
        lstm_step(z2, whp, h_lo, h_hi, c_lo, c_hi, isG, bse);
        { int tn = t + 6; if (tn >= TT) tn = 2; z2 = __ldcs(zp + tn * 32); }
        lstm_step(z3, whp, h_lo, h_hi, c_lo, c_hi, isG, bse);
        { int tn = t + 7; if (tn >= TT) tn = 3; z3 = __ldcs(zp + tn * 32); }
    }

    // ---- head MLP: all lanes compute redundantly (uniform), lane 0 stores ----
    float hv[16];
    #pragma unroll
    for (int k = 0; k < 16; k++)
        hv[k] = __shfl_sync(M, (k & 1) ? h_hi : h_lo, k >> 1);

    float a2[8];
    #pragma unroll
    for (int j = 0; j < 8; j++) {
        float s = b2[j];
        #pragma unroll
        for (int k = 0; k < 16; k++) s = fmaf(hv[k], W2[k * 8 + j], s);
        a2[j] = fmaxf(s, 0.f);
    }
    float a3[4];
    #pragma unroll
    for (int j = 0; j < 4; j++) {
        float s = b3[j];
        #pragma unroll
        for (int k = 0; k < 8; k++) s = fmaf(a2[k], W3[k * 4 + j], s);
        a3[j] = fmaxf(s, 0.f);
    }
    float so = bo[0];
    #pragma unroll
    for (int k = 0; k < 4; k++) so = fmaf(a3[k], Wo[k], so);

    if (lane == 0) out[row] = __fdividef(1.0f, 1.0f + __expf(-so));
}

// =====================================================================
extern "C" void kernel_launch(void* const* d_in, const int* in_sizes, int n_in,
                              void* d_out, int out_size) {
    const float* x  = (const float*)d_in[0];
    const float* Wx = (const float*)d_in[1];
    const float* Wh = (const float*)d_in[2];
    const float* b  = (const float*)d_in[3];
    const float* W2 = (const float*)d_in[4];
    const float* b2 = (const float*)d_in[5];
    const float* W3 = (const float*)d_in[6];
    const float* b3 = (const float*)d_in[7];
    const float* Wo = (const float*)d_in[8];
    const float* bo = (const float*)d_in[9];
    float* out = (float*)d_out;

    // 80 KB dynamic smem (> 48 KB static limit). Idempotent host-side call,
    // not a stream op -> graph-capture safe.
    cudaFuncSetAttribute(gemm_xz_kernel,
                         cudaFuncAttributeMaxDynamicSharedMemorySize, 81920);

    gemm_xz_kernel<<<BT / 128, 256, 81920>>>(x, Wx, b);
    rnn_kernel<<<BB / 4, 128>>>(Wh, W2, b2, W3, b3, Wo, bo, out);
}

// round 17
// speedup vs baseline: 1.2573x; 1.2573x over previous
#include <cuda_runtime.h>
#include <cstdint>

// Shapes (fixed by the problem)
#define BB   2048
#define TT   512
#define FF   64
#define HH   16
#define G4   64          // 4*H
#define BT   (BB*TT)     // 1,048,576 rows in the xz GEMM

// Scratch for xz = x@Wx + b : [B*T, 64] fp32 = 256 MiB (module global, allowed)
__device__ float g_xz[(size_t)BT * G4];

// ---------------- packed f32x2 helpers (family-wide PTX, sm_100+) ----------------
__device__ __forceinline__ unsigned long long pack2(float a, float b) {
    unsigned long long r;
    asm("mov.b64 %0, {%1, %2};" : "=l"(r) : "f"(a), "f"(b));
    return r;
}
__device__ __forceinline__ float2 unpack2(unsigned long long v) {
    float2 r;
    asm("mov.b64 {%0, %1}, %2;" : "=f"(r.x), "=f"(r.y) : "l"(v));
    return r;
}
__device__ __forceinline__ unsigned long long fma2(unsigned long long a,
                                                   unsigned long long b,
                                                   unsigned long long c) {
    unsigned long long d;
    asm("fma.rn.f32x2 %0, %1, %2, %3;" : "=l"(d) : "l"(a), "l"(b), "l"(c));
    return d;
}

// =====================================================================
// Kernel 1 (v2): xz = x @ Wx + b   — register-tiled, LDS-minimized.
//   CTA: 256 threads, 128 rows. Thread = 8 rows x 4 cols (2 col-pairs).
//   SMEM: xd[k][row] duplicated pairs {v,v}, k-major, stride 130 ull;
//         wp[k][colpair] packed {w[k][2c],w[k][2c+1]}.
//   Inner loop per k: 4 LDS.128 (x) + 1 LDS.128 (w) + 16 fma2
//   -> 20 LSU-issue cyc vs 32 FMA-issue cyc: FMA-bound (was LDS-bound).
// =====================================================================
#define XSTR 130                      // ull stride per k
#define XD_BYTES (64 * XSTR * 8)      // 66560
#define WP_OFF   XD_BYTES
#define SM2_TOTAL (XD_BYTES + 64 * 32 * 8)   // + 16384 = 82944

__global__ void __launch_bounds__(256, 2)
gemm_xz_kernel(const float* __restrict__ x,
               const float* __restrict__ Wx,
               const float* __restrict__ b) {
    extern __shared__ unsigned char smem[];
    unsigned long long* xd = (unsigned long long*)smem;
    unsigned long long* wp = (unsigned long long*)(smem + WP_OFF);

    const int tid = threadIdx.x;

    // ---- stage x tile (128 rows x 64 k) as duplicated pairs, k-major ----
    {
        const float4* x4 = (const float4*)x;
        size_t base4 = (size_t)blockIdx.x * 2048;       // 128 rows * 16 float4
        #pragma unroll
        for (int i = 0; i < 8; i++) {
            int idx = tid + i * 256;
            float4 v = __ldcs(&x4[base4 + idx]);
            int row = idx >> 4;
            int k0  = (idx & 15) * 4;
            xd[(k0 + 0) * XSTR + row] = pack2(v.x, v.x);
            xd[(k0 + 1) * XSTR + row] = pack2(v.y, v.y);
            xd[(k0 + 2) * XSTR + row] = pack2(v.z, v.z);
            xd[(k0 + 3) * XSTR + row] = pack2(v.w, v.w);
        }
    }
    // ---- stage Wx as packed col-pairs: wp[k][cp] = {Wx[k][2cp], Wx[k][2cp+1]} ----
    {
        const float4* w4 = (const float4*)Wx;
        #pragma unroll
        for (int i = 0; i < 4; i++) {
            int idx = tid + i * 256;              // 64 k x 16 c4
            float4 v = w4[idx];
            int k  = idx >> 4;
            int c4 = idx & 15;
            wp[k * 32 + c4 * 2]     = pack2(v.x, v.y);
            wp[k * 32 + c4 * 2 + 1] = pack2(v.z, v.w);
        }
    }
    __syncthreads();

    const int rb = (tid >> 4) * 8;        // row base: 0,8,...,120
    const int cq = tid & 15;              // col quad: cols 4cq..4cq+3
    const int cb = cq * 2;                // colpair base

    unsigned long long acc[8][2];
    {
        float4 bv = ((const float4*)b)[cq];
        unsigned long long b0 = pack2(bv.x, bv.y);
        unsigned long long b1 = pack2(bv.z, bv.w);
        #pragma unroll
        for (int r = 0; r < 8; r++) { acc[r][0] = b0; acc[r][1] = b1; }
    }

    #pragma unroll 2
    for (int k = 0; k < 64; k++) {
        const ulonglong2* xrow = (const ulonglong2*)(xd + k * XSTR + rb);
        ulonglong2 xa = xrow[0];          // rows rb+0, rb+1 (dup pairs)
        ulonglong2 xb = xrow[1];          // rb+2, rb+3
        ulonglong2 xc = xrow[2];          // rb+4, rb+5
        ulonglong2 xe = xrow[3];          // rb+6, rb+7
        ulonglong2 wv = *(const ulonglong2*)(wp + k * 32 + cb);
        acc[0][0] = fma2(xa.x, wv.x, acc[0][0]); acc[0][1] = fma2(xa.x, wv.y, acc[0][1]);
        acc[1][0] = fma2(xa.y, wv.x, acc[1][0]); acc[1][1] = fma2(xa.y, wv.y, acc[1][1]);
        acc[2][0] = fma2(xb.x, wv.x, acc[2][0]); acc[2][1] = fma2(xb.x, wv.y, acc[2][1]);
        acc[3][0] = fma2(xb.y, wv.x, acc[3][0]); acc[3][1] = fma2(xb.y, wv.y, acc[3][1]);
        acc[4][0] = fma2(xc.x, wv.x, acc[4][0]); acc[4][1] = fma2(xc.x, wv.y, acc[4][1]);
        acc[5][0] = fma2(xc.y, wv.x, acc[5][0]); acc[5][1] = fma2(xc.y, wv.y, acc[5][1]);
        acc[6][0] = fma2(xe.x, wv.x, acc[6][0]); acc[6][1] = fma2(xe.x, wv.y, acc[6][1]);
        acc[7][0] = fma2(xe.y, wv.x, acc[7][0]); acc[7][1] = fma2(xe.y, wv.y, acc[7][1]);
    }

    // ---- epilogue: coalesced 16B stores (cols 4cq..4cq+3 of each row) ----
    {
        ulonglong2* out2 = (ulonglong2*)g_xz;   // 1 ull2 = 4 floats
        size_t rowg = (size_t)blockIdx.x * 128 + rb;
        #pragma unroll
        for (int r = 0; r < 8; r++) {
            ulonglong2 o;
            o.x = acc[r][0];
            o.y = acc[r][1];
            out2[(rowg + r) * 16 + cq] = o;
        }
    }
}

// =====================================================================
// Kernel 2 (v2): LSTM recurrence + head. TWO batch rows per warp —
//   whp shared, two independent dependency chains interleaved to lift
//   issue% (was 59.3% at 1 row/warp; chains were latency-exposed).
//   Gate/lane map per row unchanged:
//     lane l owns z pair (2l,2l+1); lanes 0-7 i | 8-15 f | 16-23 g | 24-31 o
// =====================================================================
__device__ __forceinline__ float sigm(float x) {
    return __fdividef(1.0f, 1.0f + __expf(-x));
}

__device__ __forceinline__ void lstm_step(float2 z, const float2* whp,
                                          float& h_lo, float& h_hi,
                                          float& c_lo, float& c_hi,
                                          bool isG, int bse) {
    const unsigned M = 0xffffffffu;
    float alo = z.x, ahi = z.y;       // xz already includes bias
    float blo = 0.f, bhi = 0.f;       // second chain for ILP
    #pragma unroll
    for (int k = 0; k < 16; k++) {
        float hk = __shfl_sync(M, (k & 1) ? h_hi : h_lo, k >> 1);
        if (k & 2) { blo = fmaf(hk, whp[k].x, blo); bhi = fmaf(hk, whp[k].y, bhi); }
        else       { alo = fmaf(hk, whp[k].x, alo); ahi = fmaf(hk, whp[k].y, ahi); }
    }
    alo += blo; ahi += bhi;

    float act_lo = isG ? fmaxf(alo, 0.f) : sigm(alo);
    float act_hi = isG ? fmaxf(ahi, 0.f) : sigm(ahi);

    // gather f,g,o pairs onto c-owner lanes 0-7; other lanes get benign garbage
    float f_lo = __shfl_sync(M, act_lo, bse + 8);
    float f_hi = __shfl_sync(M, act_hi, bse + 8);
    float g_lo = __shfl_sync(M, act_lo, bse + 16);
    float g_hi = __shfl_sync(M, act_hi, bse + 16);
    float o_lo = __shfl_sync(M, act_lo, bse + 24);
    float o_hi = __shfl_sync(M, act_hi, bse + 24);

    c_lo = fmaf(f_lo, c_lo, act_lo * g_lo);   // act_lo == i on lanes 0-7
    c_hi = fmaf(f_hi, c_hi, act_hi * g_hi);
    h_lo = o_lo * fmaxf(c_lo, 0.f);
    h_hi = o_hi * fmaxf(c_hi, 0.f);
}

__device__ __forceinline__ float head_out(float h_lo, float h_hi,
                                          const float* W2, const float* b2,
                                          const float* W3, const float* b3,
                                          const float* Wo, const float* bo) {
    const unsigned M = 0xffffffffu;
    float hv[16];
    #pragma unroll
    for (int k = 0; k < 16; k++)
        hv[k] = __shfl_sync(M, (k & 1) ? h_hi : h_lo, k >> 1);

    float a2[8];
    #pragma unroll
    for (int j = 0; j < 8; j++) {
        float s = b2[j];
        #pragma unroll
        for (int k = 0; k < 16; k++) s = fmaf(hv[k], W2[k * 8 + j], s);
        a2[j] = fmaxf(s, 0.f);
    }
    float a3[4];
    #pragma unroll
    for (int j = 0; j < 4; j++) {
        float s = b3[j];
        #pragma unroll
        for (int k = 0; k < 8; k++) s = fmaf(a2[k], W3[k * 4 + j], s);
        a3[j] = fmaxf(s, 0.f);
    }
    float so = bo[0];
    #pragma unroll
    for (int k = 0; k < 4; k++) so = fmaf(a3[k], Wo[k], so);
    return __fdividef(1.0f, 1.0f + __expf(-so));
}

__global__ void __launch_bounds__(128)
rnn_kernel(const float* __restrict__ Wh,
           const float* __restrict__ W2, const float* __restrict__ b2,
           const float* __restrict__ W3, const float* __restrict__ b3,
           const float* __restrict__ Wo, const float* __restrict__ bo,
           float* __restrict__ out) {
    const int warp = threadIdx.x >> 5;
    const int lane = threadIdx.x & 31;
    const int rowA = (blockIdx.x * 4 + warp) * 2;     // batch rows rowA, rowA+1
    const int rowB = rowA + 1;

    // Wh column pairs for this lane's gates: {Wh[k][2l], Wh[k][2l+1]} (shared)
    float2 whp[16];
    #pragma unroll
    for (int k = 0; k < 16; k++)
        whp[k] = *(const float2*)(Wh + k * G4 + 2 * lane);

    const float2* zpA = (const float2*)g_xz + (size_t)rowA * (TT * 32) + lane;
    const float2* zpB = (const float2*)g_xz + (size_t)rowB * (TT * 32) + lane;

    // 4-deep prefetch ring per row (8 loads in flight per warp)
    float2 zA0 = __ldcs(zpA +  0), zB0 = __ldcs(zpB +  0);
    float2 zA1 = __ldcs(zpA + 32), zB1 = __ldcs(zpB + 32);
    float2 zA2 = __ldcs(zpA + 64), zB2 = __ldcs(zpB + 64);
    float2 zA3 = __ldcs(zpA + 96), zB3 = __ldcs(zpB + 96);

    float hA_lo = 0.f, hA_hi = 0.f, cA_lo = 0.f, cA_hi = 0.f;
    float hB_lo = 0.f, hB_hi = 0.f, cB_lo = 0.f, cB_hi = 0.f;
    const bool isG = (lane >= 16 && lane < 24);
    const int  bse = lane & 7;

    #pragma unroll 1
    for (int t = 0; t < TT; t += 4) {
        lstm_step(zA0, whp, hA_lo, hA_hi, cA_lo, cA_hi, isG, bse);
        lstm_step(zB0, whp, hB_lo, hB_hi, cB_lo, cB_hi, isG, bse);
        { int tn = t + 4; if (tn >= TT) tn = 0;
          zA0 = __ldcs(zpA + tn * 32); zB0 = __ldcs(zpB + tn * 32); }
        lstm_step(zA1, whp, hA_lo, hA_hi, cA_lo, cA_hi, isG, bse);
        lstm_step(zB1, whp, hB_lo, hB_hi, cB_lo, cB_hi, isG, bse);
        { int tn = t + 5; if (tn >= TT) tn = 1;
          zA1 = __ldcs(zpA + tn * 32); zB1 = __ldcs(zpB + tn * 32); }
        lstm_step(zA2, whp, hA_lo, hA_hi, cA_lo, cA_hi, isG, bse);
        lstm_step(zB2, whp, hB_lo, hB_hi, cB_lo, cB_hi, isG, bse);
        { int tn = t + 6; if (tn >= TT) tn = 2;
          zA2 = __ldcs(zpA + tn * 32); zB2 = __ldcs(zpB + tn * 32); }
        lstm_step(zA3, whp, hA_lo, hA_hi, cA_lo, cA_hi, isG, bse);
        lstm_step(zB3, whp, hB_lo, hB_hi, cB_lo, cB_hi, isG, bse);
        { int tn = t + 7; if (tn >= TT) tn = 3;
          zA3 = __ldcs(zpA + tn * 32); zB3 = __ldcs(zpB + tn * 32); }
    }

    float oA = head_out(hA_lo, hA_hi, W2, b2, W3, b3, Wo, bo);
    float oB = head_out(hB_lo, hB_hi, W2, b2, W3, b3, Wo, bo);
    if (lane == 0) { out[rowA] = oA; out[rowB] = oB; }
}

// =====================================================================
extern "C" void kernel_launch(void* const* d_in, const int* in_sizes, int n_in,
                              void* d_out, int out_size) {
    const float* x  = (const float*)d_in[0];
    const float* Wx = (const float*)d_in[1];
    const float* Wh = (const float*)d_in[2];
    const float* b  = (const float*)d_in[3];
    const float* W2 = (const float*)d_in[4];
    const float* b2 = (const float*)d_in[5];
    const float* W3 = (const float*)d_in[6];
    const float* b3 = (const float*)d_in[7];
    const float* Wo = (const float*)d_in[8];
    const float* bo = (const float*)d_in[9];
    float* out = (float*)d_out;

    // ~83 KB dynamic smem (> 48 KB static limit). Idempotent host-side call,
    // not a stream op -> graph-capture safe.
    cudaFuncSetAttribute(gemm_xz_kernel,
                         cudaFuncAttributeMaxDynamicSharedMemorySize, SM2_TOTAL);

    gemm_xz_kernel<<<BT / 128, 256, SM2_TOTAL>>>(x, Wx, b);
    rnn_kernel<<<BB / 8, 128>>>(Wh, W2, b2, W3, b3, Wo, bo, out);
}